// round 10
// baseline (speedup 1.0000x reference)
#include <cuda_runtime.h>
#include <cuda_fp16.h>
#include <mma.h>
#include <math.h>
#include <stdint.h>

using namespace nvcuda;

#define VOCAB 32000
#define EMB   512
#define HID   1024
#define BB    16
#define TT    512
#define H3    3072

// ---- recurrence smem layout (bytes) ----
#define LDHH   1040                     // halves pitch for A operands (2080 B/row)
#define A0_OFF 0
#define A1_OFF 33280
#define RINGB  66560                    // 3-stage weight ring
#define NCHK   8                        // k-chunks per step (k=128)
#define WPITCH 136
#define CH0H   (48 * WPITCH)            // 6528 halves / chunk (layer0)
#define CH1H   (96 * WPITCH)            // 13056 halves / chunk (layer1)
#define PARTB  144896                   // 12 x 256 fp32 partials
#define GIB    157184                   // 2 x 768 fp32 gi ping-pong
#define REC_SMEM 163328

#define CSTRIDE 16
#define NTHR   384

__device__ float  g_gi0[(size_t)TT * BB * H3];      // packed [t][cta][gate][256]
__device__ __half g_h016[(size_t)TT * BB * HID];    // [t][b][H]
__device__ __half g_h116[(size_t)BB * TT * HID];    // [b][t][H] (= proj A)
__device__ float  g_h0fp[2 * 64 * 256];             // fp32 carry ping-pong
__device__ float  g_h1fp[2 * 64 * 256];
__device__ __half g_wpk0[(size_t)64 * NCHK * CH0H];
__device__ __half g_wpk1[(size_t)64 * NCHK * CH1H];
__device__ __half g_emb16[(size_t)VOCAB * EMB];
__device__ __half g_wih016[(size_t)H3 * EMB];
__device__ __half g_wout16[(size_t)VOCAB * HID];
__device__ unsigned g_cnt[2 * TT * CSTRIDE];

__device__ __forceinline__ float sigmoidf_(float x) { return 1.f / (1.f + __expf(-x)); }
__device__ __forceinline__ void mbar_init(uint32_t mbar, unsigned cnt) {
    asm volatile("mbarrier.init.shared.b64 [%0], %1;" :: "r"(mbar), "r"(cnt) : "memory");
}
__device__ __forceinline__ void mbar_expect(uint32_t mbar, unsigned tx) {
    asm volatile("mbarrier.arrive.expect_tx.shared.b64 _, [%0], %1;"
                 :: "r"(mbar), "r"(tx) : "memory");
}
__device__ __forceinline__ void bulk_g2s(uint32_t sdst, const void* gsrc, unsigned bytes,
                                         uint32_t mbar) {
    asm volatile("cp.async.bulk.shared::cta.global.mbarrier::complete_tx::bytes "
                 "[%0], [%1], %2, [%3];"
                 :: "r"(sdst), "l"(gsrc), "r"(bytes), "r"(mbar) : "memory");
}
__device__ __forceinline__ void mbar_wait(uint32_t mbar, unsigned phase) {
    asm volatile(
        "{\n\t"
        ".reg .pred P1;\n\t"
        "LAB_W_%=:\n\t"
        "mbarrier.try_wait.parity.acquire.cta.shared::cta.b64 P1, [%0], %1;\n\t"
        "@P1 bra LAB_D_%=;\n\t"
        "bra LAB_W_%=;\n\t"
        "LAB_D_%=:\n\t"
        "}"
        :: "r"(mbar), "r"(phase) : "memory");
}

__global__ void zero_cnt_k(unsigned* c) {
    int i = blockIdx.x * blockDim.x + threadIdx.x;
    if (i < 2 * TT * CSTRIDE) c[i] = 0u;
}

__global__ void f32_to_f16_k(const float4* __restrict__ src, __half2* __restrict__ dst,
                             long n4) {
    long i = (long)blockIdx.x * blockDim.x + threadIdx.x;
    long stride = (long)gridDim.x * blockDim.x;
    for (; i < n4; i += stride) {
        float4 v = src[i];
        dst[2 * i]     = __floats2half2_rn(v.x, v.y);
        dst[2 * i + 1] = __floats2half2_rn(v.z, v.w);
    }
}

// repack recurrence weights -> fp16 per-CTA contiguous chunks [cta][ch][row][WPITCH]
__global__ void repack_k(const float* __restrict__ whh0,
                         const float* __restrict__ wih1, const float* __restrict__ whh1,
                         __half* __restrict__ wpk0, __half* __restrict__ wpk1)
{
    const long tot0 = 64L * NCHK * CH0H, tot1 = 64L * NCHK * CH1H;
    long i = (long)blockIdx.x * blockDim.x + threadIdx.x;
    const long stride = (long)gridDim.x * blockDim.x;
    for (; i < tot0 + tot1; i += stride) {
        if (i < tot0) {
            long r = i; int k = (int)(r % WPITCH); r /= WPITCH;
            int row = (int)(r % 48); r /= 48;
            int ch = (int)(r % NCHK); int cta = (int)(r / NCHK);
            __half v = __float2half(0.f);
            if (k < 128)
                v = __float2half_rn(
                    whh0[((size_t)((row >> 4) * HID + cta * 16 + (row & 15))) * HID
                         + ch * 128 + k]);
            wpk0[i] = v;
        } else {
            long r = i - tot0; int k = (int)(r % WPITCH); r /= WPITCH;
            int row = (int)(r % 96); r /= 96;
            int ch = (int)(r % NCHK); int cta = (int)(r / NCHK);
            __half v = __float2half(0.f);
            if (k < 128) {
                const float* W = (row < 48) ? wih1 : whh1;
                int rr = (row < 48) ? row : row - 48;
                v = __float2half_rn(
                    W[((size_t)((rr >> 4) * HID + cta * 16 + (rr & 15))) * HID
                      + ch * 128 + k]);
            }
            wpk1[i - tot0] = v;
        }
    }
}

__global__ void tail_copy_k(const float* __restrict__ h0fp,
                            const float* __restrict__ h1fp,
                            float* __restrict__ out) {
    int i = blockIdx.x * blockDim.x + threadIdx.x;
    if (i < BB * HID) {
        int b = i >> 10, j = i & 1023;
        int cta = j >> 4, o = b * 16 + (j & 15);
        out[(size_t)BB * TT * VOCAB + i]            = h0fp[16384 + cta * 256 + o];
        out[(size_t)BB * TT * VOCAB + BB * HID + i] = h1fp[16384 + cta * 256 + o];
    }
}

// ---------------------------------------------------------------------------
// fp16 WMMA GEMM (fp32 accum), 128x128 tiles, 2-stage bulk ring, 2 CTAs/SM.
// ---------------------------------------------------------------------------
template <int GATHER, int STORE_GI>
__global__ void __launch_bounds__(256, 2)
gemm_fp16(const __half* __restrict__ A, const int* __restrict__ seq,
          const __half* __restrict__ Bm, const float* __restrict__ bias,
          float* __restrict__ C, int M, int N, int K, int lda)
{
    extern __shared__ __half hsm[];
    __shared__ float biasS[16][136];
    __shared__ int tokS[128];
    __shared__ __align__(8) unsigned long long mb_[2];

    const int tid = threadIdx.x;
    const int m0 = blockIdx.x * 128;
    const int n0 = blockIdx.y * 128;

    if (GATHER && tid < 128) {
        int m = m0 + tid;
        tokS[tid] = seq[(m & 15) * TT + (m >> 4)];
    }
    for (int i = tid; i < 2048; i += 256)
        biasS[i >> 7][i & 127] = bias[n0 + (i & 127)];

    const uint32_t sb = (uint32_t)__cvta_generic_to_shared(hsm);
    const uint32_t mbb = (uint32_t)__cvta_generic_to_shared(mb_);
    const int KC = K >> 6;

    if (tid == 0) {
        mbar_init(mbb, 1); mbar_init(mbb + 8, 1);
        mbar_expect(mbb, 32768u); mbar_expect(mbb + 8, 32768u);
    }
    __syncthreads();

    auto issue = [&](int kc, int st) {
        const int k0 = kc << 6;
        const int row = tid & 127;
        const uint32_t stb = sb + (uint32_t)st * 36864u;
        if (tid < 128) {
            const __half* src = GATHER ? (A + (size_t)tokS[row] * lda + k0)
                                       : (A + (size_t)(m0 + row) * lda + k0);
            bulk_g2s(stb + row * 144u, src, 128u, mbb + 8u * st);
        } else {
            bulk_g2s(stb + 18432u + row * 144u,
                     Bm + (size_t)(n0 + row) * K + k0, 128u, mbb + 8u * st);
        }
    };
    issue(0, 0);
    issue(1, 1);

    const int warpId = tid >> 5;
    const int wm = warpId >> 1;
    const int wn = warpId & 1;

    wmma::fragment<wmma::accumulator, 16, 16, 16, float> acc[2][4];
#pragma unroll
    for (int mi = 0; mi < 2; mi++)
#pragma unroll
        for (int ni = 0; ni < 4; ni++)
            wmma::load_matrix_sync(acc[mi][ni], &biasS[0][wn * 64 + ni * 16], 136,
                                   wmma::mem_row_major);

    for (int kc = 0; kc < KC; kc++) {
        const int st = kc & 1;
        mbar_wait(mbb + 8u * st, (unsigned)((kc >> 1) & 1));
        const __half* As = hsm + st * 18432;
        const __half* Bs = As + 9216;
#pragma unroll
        for (int ks = 0; ks < 4; ks++) {
            wmma::fragment<wmma::matrix_a, 16, 16, 16, __half, wmma::row_major> a[2];
            wmma::fragment<wmma::matrix_b, 16, 16, 16, __half, wmma::col_major> b[4];
#pragma unroll
            for (int mi = 0; mi < 2; mi++)
                wmma::load_matrix_sync(a[mi], As + (wm * 32 + mi * 16) * 72 + ks * 16, 72);
#pragma unroll
            for (int ni = 0; ni < 4; ni++)
                wmma::load_matrix_sync(b[ni], Bs + (wn * 64 + ni * 16) * 72 + ks * 16, 72);
#pragma unroll
            for (int mi = 0; mi < 2; mi++)
#pragma unroll
                for (int ni = 0; ni < 4; ni++)
                    wmma::mma_sync(acc[mi][ni], a[mi], b[ni], acc[mi][ni]);
        }
        __syncthreads();
        if (kc + 2 < KC) {
            if (tid == 0) mbar_expect(mbb + 8u * st, 32768u);
            __syncthreads();
            issue(kc + 2, st);
        }
    }

#pragma unroll
    for (int mi = 0; mi < 2; mi++)
#pragma unroll
        for (int ni = 0; ni < 4; ni++) {
            int mrow = m0 + wm * 32 + mi * 16;
            int ncol = n0 + wn * 64 + ni * 16;
            if (STORE_GI) {
                int t = mrow >> 4;
                int gate = ncol >> 10;
                int colblk = (ncol & 1023) >> 4;
                wmma::store_matrix_sync(
                    C + (((size_t)t * 64 + colblk) * 3 + gate) * 256,
                    acc[mi][ni], 16, wmma::mem_row_major);
            } else {
                wmma::store_matrix_sync(C + (size_t)mrow * N + ncol,
                                        acc[mi][ni], N, wmma::mem_row_major);
            }
        }
}

// ---------------------------------------------------------------------------
// Persistent fp16 GRU: 128 CTAs x 384 thr (12 warps), 1 CTA/SM.
// K-dot split across warps: layer0 warp=(gate, K/4), layer1 warp=(slot, K/2).
// ---------------------------------------------------------------------------
__global__ void __launch_bounds__(NTHR, 1)
gru_persistent(const float* __restrict__ gi0,
               const __half* __restrict__ wpk0, const float* __restrict__ bhh0,
               const __half* __restrict__ wpk1, const float* __restrict__ bih1,
               const float* __restrict__ bhh1,
               __half* __restrict__ h016, __half* __restrict__ h116,
               float* __restrict__ h0fp, float* __restrict__ h1fp,
               unsigned* __restrict__ cnt)
{
    extern __shared__ char smraw[];
    __half* smA0 = (__half*)smraw;
    __half* smA1 = (__half*)(smraw + A1_OFF);
    __half* ring = (__half*)(smraw + RINGB);
    float*  P    = (float*)(smraw + PARTB);
    float*  GIS  = (float*)(smraw + GIB);
    __shared__ __align__(8) unsigned long long mbars[5];

    const int tid = threadIdx.x;
    const int w = tid >> 5;
    const bool isA = blockIdx.x < 64;
    const int cta = isA ? blockIdx.x : (blockIdx.x - 64);
    const int c0 = cta * 16;
    volatile unsigned* vc = cnt;

    // warp work mapping
    const int gslot = isA ? (w >> 2) : (w >> 1);   // layer0: gate 0..2, layer1: slot 0..5
    const int ksel  = isA ? (w & 3) : (w & 1);
    const int kmask = isA ? 3 : 1;

    const __half* wbase = isA ? (wpk0 + (size_t)cta * NCHK * CH0H)
                              : (wpk1 + (size_t)cta * NCHK * CH1H);
    const int chH = isA ? CH0H : CH1H;
    const unsigned chBytes = (unsigned)(chH * 2);

    const uint32_t smb = (uint32_t)__cvta_generic_to_shared(smraw);
    const uint32_t mbb = (uint32_t)__cvta_generic_to_shared(mbars);

    // per-thread epilogue biases (tid < 256)
    const int bb = (tid & 255) >> 4, jl = tid & 15;
    const int j = c0 + jl;
    float B0r = 0.f, B0u = 0.f, B0n = 0.f;
    float B1ir = 0.f, B1iu = 0.f, B1in = 0.f, B1hr = 0.f, B1hu = 0.f, B1hn = 0.f;
    if (tid < 256) {
        if (isA) {
            B0r = bhh0[j]; B0u = bhh0[HID + j]; B0n = bhh0[2 * HID + j];
        } else {
            B1ir = bih1[j]; B1iu = bih1[HID + j]; B1in = bih1[2 * HID + j];
            B1hr = bhh1[j]; B1hu = bhh1[HID + j]; B1hn = bhh1[2 * HID + j];
        }
    }

    if (tid == 0) {
        for (int s = 0; s < 5; s++) mbar_init(mbb + 8 * s, 1);
#pragma unroll
        for (int s = 0; s < 3; s++) {
            mbar_expect(mbb + 8 * s, chBytes);
            bulk_g2s(smb + RINGB + (uint32_t)s * chBytes, wbase + (size_t)s * chH,
                     chBytes, mbb + 8 * s);
        }
        if (isA) {
            mbar_expect(mbb + 32, 3072u);
            bulk_g2s(smb + GIB, gi0 + (size_t)cta * 3 * 256, 3072u, mbb + 32);
        }
    }
    __syncthreads();

    int ws = 0;
    unsigned wpar = 0;
    long gc = 0;
    const long GCMAX = (long)TT * NCHK;
    int hph = 0;

    wmma::fragment<wmma::accumulator, 16, 16, 16, float> acc0, acc1;

    for (int t = 0; t < TT; t++) {
        // ---- handoff spin ----
        if (tid == 0) {
            unsigned sp;
            if (isA) {
                if (t) { sp = 0; while (vc[(t - 1) * CSTRIDE] < 64u) { if (++sp > 16) __nanosleep(32); } }
            } else {
                sp = 0; while (vc[t * CSTRIDE] < 64u) { if (++sp > 16) __nanosleep(32); }
                if (t) { sp = 0; while (vc[(TT + t - 1) * CSTRIDE] < 64u) { if (++sp > 16) __nanosleep(32); } }
            }
        }
        __syncthreads();
        __threadfence();

        // ---- stage fp16 A operands ----
        if (isA) {
            if (t == 0) {
                for (int i = tid; i < 8320; i += NTHR) ((uint32_t*)smA0)[i] = 0u;
                __syncthreads();
            } else {
                if (tid == 0) mbar_expect(mbb + 24, 32768u);
                __syncthreads();
                if (tid < 16)
                    bulk_g2s(smb + A0_OFF + tid * 2080u,
                             h016 + ((size_t)(t - 1) * BB + tid) * HID, 2048u, mbb + 24);
                mbar_wait(mbb + 24, (unsigned)(hph & 1));
                hph++;
                __syncthreads();
            }
        } else {
            if (tid == 0) mbar_expect(mbb + 24, t > 0 ? 65536u : 32768u);
            __syncthreads();
            if (t == 0) {
                for (int i = tid; i < 8320; i += NTHR) ((uint32_t*)smA1)[i] = 0u;
            }
            if (tid < 16)
                bulk_g2s(smb + A0_OFF + tid * 2080u,
                         h016 + ((size_t)t * BB + tid) * HID, 2048u, mbb + 24);
            if (t > 0 && tid >= 16 && tid < 32) {
                int b = tid - 16;
                bulk_g2s(smb + A1_OFF + b * 2080u,
                         h116 + ((size_t)b * TT + (t - 1)) * HID, 2048u, mbb + 24);
            }
            mbar_wait(mbb + 24, (unsigned)(hph & 1));
            hph++;
            __syncthreads();
        }

        float hprev = 0.f;
        if (t > 0 && tid < 256)
            hprev = (isA ? h0fp : h1fp)[((t + 1) & 1) * 16384 + cta * 256 + tid];

        // ---- K loop: 8 chunks, each warp takes chunks with (ch & kmask) == ksel ----
        wmma::fill_fragment(acc0, 0.f);
        wmma::fill_fragment(acc1, 0.f);
        const __half* Ab = (isA || gslot < 3) ? smA0 : smA1;
        const __half* Bw = nullptr;

        for (int ch = 0; ch < NCHK; ch++) {
            mbar_wait(mbb + 8 * ws, wpar);
            if ((ch & kmask) == ksel) {
                const __half* Ap = Ab + (ch << 7);
                const __half* Bp = ring + ws * chH + gslot * 16 * WPITCH;
#pragma unroll
                for (int ks = 0; ks < 8; ks++) {
                    wmma::fragment<wmma::matrix_a, 16, 16, 16, __half, wmma::row_major> af;
                    wmma::fragment<wmma::matrix_b, 16, 16, 16, __half, wmma::col_major> bf;
                    wmma::load_matrix_sync(af, Ap + ks * 16, LDHH);
                    wmma::load_matrix_sync(bf, Bp + ks * 16, WPITCH);
                    if (ks & 1) wmma::mma_sync(acc1, af, bf, acc1);
                    else        wmma::mma_sync(acc0, af, bf, acc0);
                }
            }
            __syncthreads();
            if (tid == 0 && gc + 3 < GCMAX) {
                int nch = (int)((gc + 3) & (NCHK - 1));
                mbar_expect(mbb + 8 * ws, chBytes);
                bulk_g2s(smb + RINGB + (uint32_t)ws * chBytes,
                         wbase + (size_t)nch * chH, chBytes, mbb + 8 * ws);
            }
            gc++;
            ws++;
            if (ws == 3) { ws = 0; wpar ^= 1u; }
        }

        // ---- epilogue ----
        {
#pragma unroll
            for (int e = 0; e < acc0.num_elements; e++) acc0.x[e] += acc1.x[e];
            wmma::store_matrix_sync(P + w * 256, acc0, 16, wmma::mem_row_major);
        }
        __syncthreads();
        if (isA) mbar_wait(mbb + 32, (unsigned)(t & 1));

        if (tid < 256) {
            const int o = tid;
            if (isA) {
                // gate g partial = sum over quarters q of P[(g*4+q)*256 + o]
                float Gr = P[o] + P[256 + o] + P[512 + o] + P[768 + o];
                float Gu = P[1024 + o] + P[1280 + o] + P[1536 + o] + P[1792 + o];
                float Gn = P[2048 + o] + P[2304 + o] + P[2560 + o] + P[2816 + o];
                const float* gis = GIS + (t & 1) * 768;
                float r = sigmoidf_(gis[o] + Gr + B0r);
                float u = sigmoidf_(gis[256 + o] + Gu + B0u);
                float n = tanhf(gis[512 + o] + r * (Gn + B0n));
                float hnew = (1.f - u) * n + u * hprev;
                h016[((size_t)t * BB + bb) * HID + j] = __float2half_rn(hnew);
                h0fp[(t & 1) * 16384 + cta * 256 + o] = hnew;
            } else {
                // slot s partial = P[(2s)*256+o] + P[(2s+1)*256+o]
                float Gir = P[o] + P[256 + o];
                float Giu = P[512 + o] + P[768 + o];
                float Gin = P[1024 + o] + P[1280 + o];
                float Ghr = P[1536 + o] + P[1792 + o];
                float Ghu = P[2048 + o] + P[2304 + o];
                float Ghn = P[2560 + o] + P[2816 + o];
                float r = sigmoidf_(Gir + B1ir + Ghr + B1hr);
                float u = sigmoidf_(Giu + B1iu + Ghu + B1hu);
                float n = tanhf(Gin + B1in + r * (Ghn + B1hn));
                float hnew = (1.f - u) * n + u * hprev;
                h116[((size_t)bb * TT + t) * HID + j] = __float2half_rn(hnew);
                h1fp[(t & 1) * 16384 + cta * 256 + o] = hnew;
            }
        }
        __threadfence();
        __syncthreads();
        if (tid == 0) {
            atomicAdd(&cnt[((isA ? 0 : TT) + t) * CSTRIDE], 1u);
            if (isA && t + 1 < TT) {
                mbar_expect(mbb + 32, 3072u);
                bulk_g2s(smb + GIB + (uint32_t)(((t + 1) & 1) * 3072),
                         gi0 + ((size_t)(t + 1) * 64 + cta) * 3 * 256, 3072u, mbb + 32);
            }
        }
        __syncthreads();
        (void)Bw;
    }
}

extern "C" void kernel_launch(void* const* d_in, const int* in_sizes, int n_in,
                              void* d_out, int out_size)
{
    const int*   seq  = (const int*)d_in[0];
    const float* emb  = (const float*)d_in[1];
    const float* wih0 = (const float*)d_in[2];
    const float* whh0 = (const float*)d_in[3];
    const float* bih0 = (const float*)d_in[4];
    const float* bhh0 = (const float*)d_in[5];
    const float* wih1 = (const float*)d_in[6];
    const float* whh1 = (const float*)d_in[7];
    const float* bih1 = (const float*)d_in[8];
    const float* bhh1 = (const float*)d_in[9];
    const float* wout = (const float*)d_in[10];
    const float* bout = (const float*)d_in[11];
    float* out = (float*)d_out;

    float *gi0, *h0fp, *h1fp; __half *h016, *h116, *wpk0, *wpk1, *emb16, *wih016, *wout16;
    unsigned* cnt;
    cudaGetSymbolAddress((void**)&gi0,    g_gi0);
    cudaGetSymbolAddress((void**)&h016,   g_h016);
    cudaGetSymbolAddress((void**)&h116,   g_h116);
    cudaGetSymbolAddress((void**)&h0fp,   g_h0fp);
    cudaGetSymbolAddress((void**)&h1fp,   g_h1fp);
    cudaGetSymbolAddress((void**)&wpk0,   g_wpk0);
    cudaGetSymbolAddress((void**)&wpk1,   g_wpk1);
    cudaGetSymbolAddress((void**)&emb16,  g_emb16);
    cudaGetSymbolAddress((void**)&wih016, g_wih016);
    cudaGetSymbolAddress((void**)&wout16, g_wout16);
    cudaGetSymbolAddress((void**)&cnt,    g_cnt);

    const int gemm_smem = 73728;
    cudaFuncSetAttribute((const void*)gemm_fp16<1, 1>,
                         cudaFuncAttributeMaxDynamicSharedMemorySize, gemm_smem);
    cudaFuncSetAttribute((const void*)gemm_fp16<0, 0>,
                         cudaFuncAttributeMaxDynamicSharedMemorySize, gemm_smem);
    cudaFuncSetAttribute((const void*)gru_persistent,
                         cudaFuncAttributeMaxDynamicSharedMemorySize, REC_SMEM);

    zero_cnt_k<<<64, 256>>>(cnt);
    f32_to_f16_k<<<4096, 256>>>((const float4*)emb,  (__half2*)emb16,  (long)VOCAB * EMB / 4);
    f32_to_f16_k<<<2048, 256>>>((const float4*)wih0, (__half2*)wih016, (long)H3 * EMB / 4);
    f32_to_f16_k<<<4096, 256>>>((const float4*)wout, (__half2*)wout16, (long)VOCAB * HID / 4);
    repack_k<<<4096, 256>>>(whh0, wih1, whh1, wpk0, wpk1);

    // gi0 packed = gather(emb16) @ wih016^T + b_ih0
    {
        dim3 g(64, H3 / 128);
        gemm_fp16<1, 1><<<g, 256, gemm_smem>>>(emb16, seq, wih016, bih0, gi0,
                                               BB * TT, H3, EMB, EMB);
    }

    gru_persistent<<<128, NTHR, REC_SMEM>>>(gi0, wpk0, bhh0, wpk1, bih1, bhh1,
                                            h016, h116, h0fp, h1fp, cnt);

    tail_copy_k<<<(BB * HID + 255) / 256, 256>>>(h0fp, h1fp, out);

    // logits = h116 @ wout16^T + b_out
    {
        dim3 g(64, VOCAB / 128);
        gemm_fp16<0, 0><<<g, 256, gemm_smem>>>(h116, nullptr, wout16, bout, out,
                                               BB * TT, VOCAB, HID, HID);
    }
}

// round 12
// speedup vs baseline: 1.0885x; 1.0885x over previous
#include <cuda_runtime.h>
#include <cuda_fp16.h>
#include <mma.h>
#include <math.h>
#include <stdint.h>

using namespace nvcuda;

#define VOCAB 32000
#define EMB   512
#define HID   1024
#define BB    16
#define TT    512
#define H3    3072

// ---- recurrence smem layout (bytes) ----
#define LDHH   1040                     // halves pitch for A operands
#define A0_OFF 0
#define A1_OFF 33280
#define RINGB  66560                    // 2-stage weight ring
#define NCHK   4                        // k-chunks per step (k=256)
#define WPITCH 264                      // halves per packed weight row (256 + 8 pad)
#define CH0H   (48 * WPITCH)            // 12672 halves / chunk (layer0)
#define CH1H   (96 * WPITCH)            // 25344 halves / chunk (layer1)
#define PARTB  167936                   // 6 x 256 fp32 partials
#define GIB    174080                   // 2 x 768 fp32 gi ping-pong
#define REC_SMEM 180224

#define CSTRIDE 16

__device__ float  g_gi0[(size_t)TT * BB * H3];      // packed [t][cta][gate][256]
__device__ __half g_h016[(size_t)TT * BB * HID];    // [t][b][H]
__device__ __half g_h116[(size_t)BB * TT * HID];    // [b][t][H] (= proj A)
__device__ float  g_h0fp[2 * 64 * 256];             // fp32 carry ping-pong
__device__ float  g_h1fp[2 * 64 * 256];
__device__ __half g_wpk0[(size_t)64 * NCHK * CH0H];
__device__ __half g_wpk1[(size_t)64 * NCHK * CH1H];
__device__ __half g_emb16[(size_t)VOCAB * EMB];
__device__ __half g_wih016[(size_t)H3 * EMB];
__device__ __half g_wout16[(size_t)VOCAB * HID];
__device__ unsigned g_cnt[2 * TT * CSTRIDE];

__device__ __forceinline__ float sigmoidf_(float x) { return 1.f / (1.f + __expf(-x)); }
__device__ __forceinline__ void mbar_init(uint32_t mbar, unsigned cnt) {
    asm volatile("mbarrier.init.shared.b64 [%0], %1;" :: "r"(mbar), "r"(cnt) : "memory");
}
__device__ __forceinline__ void mbar_expect(uint32_t mbar, unsigned tx) {
    asm volatile("mbarrier.arrive.expect_tx.shared.b64 _, [%0], %1;"
                 :: "r"(mbar), "r"(tx) : "memory");
}
__device__ __forceinline__ void bulk_g2s(uint32_t sdst, const void* gsrc, unsigned bytes,
                                         uint32_t mbar) {
    asm volatile("cp.async.bulk.shared::cta.global.mbarrier::complete_tx::bytes "
                 "[%0], [%1], %2, [%3];"
                 :: "r"(sdst), "l"(gsrc), "r"(bytes), "r"(mbar) : "memory");
}
__device__ __forceinline__ void mbar_wait(uint32_t mbar, unsigned phase) {
    asm volatile(
        "{\n\t"
        ".reg .pred P1;\n\t"
        "LAB_W_%=:\n\t"
        "mbarrier.try_wait.parity.acquire.cta.shared::cta.b64 P1, [%0], %1;\n\t"
        "@P1 bra LAB_D_%=;\n\t"
        "bra LAB_W_%=;\n\t"
        "LAB_D_%=:\n\t"
        "}"
        :: "r"(mbar), "r"(phase) : "memory");
}

__global__ void zero_cnt_k(unsigned* c) {
    int i = blockIdx.x * blockDim.x + threadIdx.x;
    if (i < 2 * TT * CSTRIDE) c[i] = 0u;
}

__global__ void f32_to_f16_k(const float4* __restrict__ src, __half2* __restrict__ dst,
                             long n4) {
    long i = (long)blockIdx.x * blockDim.x + threadIdx.x;
    long stride = (long)gridDim.x * blockDim.x;
    for (; i < n4; i += stride) {
        float4 v = src[i];
        dst[2 * i]     = __floats2half2_rn(v.x, v.y);
        dst[2 * i + 1] = __floats2half2_rn(v.z, v.w);
    }
}

// repack recurrence weights -> fp16 per-CTA contiguous chunks [cta][ch][row][WPITCH]
__global__ void repack_k(const float* __restrict__ whh0,
                         const float* __restrict__ wih1, const float* __restrict__ whh1,
                         __half* __restrict__ wpk0, __half* __restrict__ wpk1)
{
    const long tot0 = 64L * NCHK * CH0H, tot1 = 64L * NCHK * CH1H;
    long i = (long)blockIdx.x * blockDim.x + threadIdx.x;
    const long stride = (long)gridDim.x * blockDim.x;
    for (; i < tot0 + tot1; i += stride) {
        if (i < tot0) {
            long r = i; int k = (int)(r % WPITCH); r /= WPITCH;
            int row = (int)(r % 48); r /= 48;
            int ch = (int)(r % NCHK); int cta = (int)(r / NCHK);
            __half v = __float2half(0.f);
            if (k < 256)
                v = __float2half_rn(
                    whh0[((size_t)((row >> 4) * HID + cta * 16 + (row & 15))) * HID
                         + ch * 256 + k]);
            wpk0[i] = v;
        } else {
            long r = i - tot0; int k = (int)(r % WPITCH); r /= WPITCH;
            int row = (int)(r % 96); r /= 96;
            int ch = (int)(r % NCHK); int cta = (int)(r / NCHK);
            __half v = __float2half(0.f);
            if (k < 256) {
                const float* W = (row < 48) ? wih1 : whh1;
                int rr = (row < 48) ? row : row - 48;
                v = __float2half_rn(
                    W[((size_t)((rr >> 4) * HID + cta * 16 + (rr & 15))) * HID
                      + ch * 256 + k]);
            }
            wpk1[i - tot0] = v;
        }
    }
}

__global__ void tail_copy_k(const float* __restrict__ h0fp,
                            const float* __restrict__ h1fp,
                            float* __restrict__ out) {
    int i = blockIdx.x * blockDim.x + threadIdx.x;
    if (i < BB * HID) {
        int b = i >> 10, j = i & 1023;
        int cta = j >> 4, o = b * 16 + (j & 15);
        out[(size_t)BB * TT * VOCAB + i]            = h0fp[16384 + cta * 256 + o];
        out[(size_t)BB * TT * VOCAB + BB * HID + i] = h1fp[16384 + cta * 256 + o];
    }
}

// ---------------------------------------------------------------------------
// fp16 WMMA GEMM (fp32 accum), 128x128 tiles, 2-stage bulk ring, 2 CTAs/SM.
// ---------------------------------------------------------------------------
template <int GATHER, int STORE_GI>
__global__ void __launch_bounds__(256, 2)
gemm_fp16(const __half* __restrict__ A, const int* __restrict__ seq,
          const __half* __restrict__ Bm, const float* __restrict__ bias,
          float* __restrict__ C, int M, int N, int K, int lda)
{
    extern __shared__ __half hsm[];
    __shared__ float biasS[16][136];
    __shared__ int tokS[128];
    __shared__ __align__(8) unsigned long long mb_[2];

    const int tid = threadIdx.x;
    const int m0 = blockIdx.x * 128;
    const int n0 = blockIdx.y * 128;

    if (GATHER && tid < 128) {
        int m = m0 + tid;
        tokS[tid] = seq[(m & 15) * TT + (m >> 4)];
    }
    for (int i = tid; i < 2048; i += 256)
        biasS[i >> 7][i & 127] = bias[n0 + (i & 127)];

    const uint32_t sb = (uint32_t)__cvta_generic_to_shared(hsm);
    const uint32_t mbb = (uint32_t)__cvta_generic_to_shared(mb_);
    const int KC = K >> 6;

    if (tid == 0) {
        mbar_init(mbb, 1); mbar_init(mbb + 8, 1);
        mbar_expect(mbb, 32768u); mbar_expect(mbb + 8, 32768u);
    }
    __syncthreads();

    auto issue = [&](int kc, int st) {
        const int k0 = kc << 6;
        const int row = tid & 127;
        const uint32_t stb = sb + (uint32_t)st * 36864u;
        if (tid < 128) {
            const __half* src = GATHER ? (A + (size_t)tokS[row] * lda + k0)
                                       : (A + (size_t)(m0 + row) * lda + k0);
            bulk_g2s(stb + row * 144u, src, 128u, mbb + 8u * st);
        } else {
            bulk_g2s(stb + 18432u + row * 144u,
                     Bm + (size_t)(n0 + row) * K + k0, 128u, mbb + 8u * st);
        }
    };
    issue(0, 0);
    issue(1, 1);

    const int warpId = tid >> 5;
    const int wm = warpId >> 1;
    const int wn = warpId & 1;

    wmma::fragment<wmma::accumulator, 16, 16, 16, float> acc[2][4];
#pragma unroll
    for (int mi = 0; mi < 2; mi++)
#pragma unroll
        for (int ni = 0; ni < 4; ni++)
            wmma::load_matrix_sync(acc[mi][ni], &biasS[0][wn * 64 + ni * 16], 136,
                                   wmma::mem_row_major);

    for (int kc = 0; kc < KC; kc++) {
        const int st = kc & 1;
        mbar_wait(mbb + 8u * st, (unsigned)((kc >> 1) & 1));
        const __half* As = hsm + st * 18432;
        const __half* Bs = As + 9216;
#pragma unroll
        for (int ks = 0; ks < 4; ks++) {
            wmma::fragment<wmma::matrix_a, 16, 16, 16, __half, wmma::row_major> a[2];
            wmma::fragment<wmma::matrix_b, 16, 16, 16, __half, wmma::col_major> b[4];
#pragma unroll
            for (int mi = 0; mi < 2; mi++)
                wmma::load_matrix_sync(a[mi], As + (wm * 32 + mi * 16) * 72 + ks * 16, 72);
#pragma unroll
            for (int ni = 0; ni < 4; ni++)
                wmma::load_matrix_sync(b[ni], Bs + (wn * 64 + ni * 16) * 72 + ks * 16, 72);
#pragma unroll
            for (int mi = 0; mi < 2; mi++)
#pragma unroll
                for (int ni = 0; ni < 4; ni++)
                    wmma::mma_sync(acc[mi][ni], a[mi], b[ni], acc[mi][ni]);
        }
        __syncthreads();
        if (kc + 2 < KC) {
            if (tid == 0) mbar_expect(mbb + 8u * st, 32768u);
            __syncthreads();
            issue(kc + 2, st);
        }
    }

#pragma unroll
    for (int mi = 0; mi < 2; mi++)
#pragma unroll
        for (int ni = 0; ni < 4; ni++) {
            int mrow = m0 + wm * 32 + mi * 16;
            int ncol = n0 + wn * 64 + ni * 16;
            if (STORE_GI) {
                int t = mrow >> 4;
                int gate = ncol >> 10;
                int colblk = (ncol & 1023) >> 4;
                wmma::store_matrix_sync(
                    C + (((size_t)t * 64 + colblk) * 3 + gate) * 256,
                    acc[mi][ni], 16, wmma::mem_row_major);
            } else {
                wmma::store_matrix_sync(C + (size_t)mrow * N + ncol,
                                        acc[mi][ni], N, wmma::mem_row_major);
            }
        }
}

// ---------------------------------------------------------------------------
// Persistent fp16 GRU: 128 CTAs x 256 thr, 1 CTA/SM.
// k-chunk 256 (4 chunks/step), 2-stage bulk ring. fp32 carry side arrays.
// ---------------------------------------------------------------------------
__global__ void __launch_bounds__(256, 1)
gru_persistent(const float* __restrict__ gi0,
               const __half* __restrict__ wpk0, const float* __restrict__ bhh0,
               const __half* __restrict__ wpk1, const float* __restrict__ bih1,
               const float* __restrict__ bhh1,
               __half* __restrict__ h016, __half* __restrict__ h116,
               float* __restrict__ h0fp, float* __restrict__ h1fp,
               unsigned* __restrict__ cnt)
{
    extern __shared__ char smraw[];
    __half* smA0 = (__half*)smraw;
    __half* smA1 = (__half*)(smraw + A1_OFF);
    __half* ring = (__half*)(smraw + RINGB);
    float*  P    = (float*)(smraw + PARTB);
    float*  GIS  = (float*)(smraw + GIB);
    __shared__ __align__(8) unsigned long long mbars[4];  // 0-1 wring, 2 oper, 3 gi

    const int tid = threadIdx.x;
    const int w = tid >> 5;
    const bool isA = blockIdx.x < 64;
    const int cta = isA ? blockIdx.x : (blockIdx.x - 64);
    const int c0 = cta * 16;
    const int ncw = isA ? 3 : 6;
    const int bb = tid >> 4, jl = tid & 15;
    const int j = c0 + jl;
    volatile unsigned* vc = cnt;

    const __half* wbase = isA ? (wpk0 + (size_t)cta * NCHK * CH0H)
                              : (wpk1 + (size_t)cta * NCHK * CH1H);
    const int chH = isA ? CH0H : CH1H;
    const unsigned chBytes = (unsigned)(chH * 2);

    const uint32_t smb = (uint32_t)__cvta_generic_to_shared(smraw);
    const uint32_t mbb = (uint32_t)__cvta_generic_to_shared(mbars);

    float B0r = 0.f, B0u = 0.f, B0n = 0.f;
    float B1ir = 0.f, B1iu = 0.f, B1in = 0.f, B1hr = 0.f, B1hu = 0.f, B1hn = 0.f;
    if (isA) {
        B0r = bhh0[j]; B0u = bhh0[HID + j]; B0n = bhh0[2 * HID + j];
    } else {
        B1ir = bih1[j]; B1iu = bih1[HID + j]; B1in = bih1[2 * HID + j];
        B1hr = bhh1[j]; B1hu = bhh1[HID + j]; B1hn = bhh1[2 * HID + j];
    }

    if (tid == 0) {
        for (int s = 0; s < 4; s++) mbar_init(mbb + 8 * s, 1);
        // prologue: weight chunks 0,1 into stages 0,1
#pragma unroll
        for (int s = 0; s < 2; s++) {
            mbar_expect(mbb + 8 * s, chBytes);
            bulk_g2s(smb + RINGB + (uint32_t)s * chBytes, wbase + (size_t)s * chH,
                     chBytes, mbb + 8 * s);
        }
        if (isA) {
            mbar_expect(mbb + 24, 3072u);
            bulk_g2s(smb + GIB, gi0 + (size_t)cta * 3 * 256, 3072u, mbb + 24);
        }
    }
    __syncthreads();

    int ws = 0;
    unsigned wpar = 0;
    long gc = 0;
    const long GCMAX = (long)TT * NCHK;
    int hph = 0;

    wmma::fragment<wmma::accumulator, 16, 16, 16, float> acc0, acc1;

    for (int t = 0; t < TT; t++) {
        // ---- handoff spin ----
        if (tid == 0) {
            unsigned sp;
            if (isA) {
                if (t) { sp = 0; while (vc[(t - 1) * CSTRIDE] < 64u) { if (++sp > 16) __nanosleep(32); } }
            } else {
                sp = 0; while (vc[t * CSTRIDE] < 64u) { if (++sp > 16) __nanosleep(32); }
                if (t) { sp = 0; while (vc[(TT + t - 1) * CSTRIDE] < 64u) { if (++sp > 16) __nanosleep(32); } }
            }
        }
        __syncthreads();
        __threadfence();

        // ---- stage fp16 A operands ----
        if (isA) {
            if (t == 0) {
                for (int i = tid; i < 8320; i += 256) ((uint32_t*)smA0)[i] = 0u;
                __syncthreads();
            } else {
                if (tid == 0) mbar_expect(mbb + 16, 32768u);
                __syncthreads();
                if (tid < 16)
                    bulk_g2s(smb + A0_OFF + tid * 2080u,
                             h016 + ((size_t)(t - 1) * BB + tid) * HID, 2048u, mbb + 16);
                mbar_wait(mbb + 16, (unsigned)(hph & 1));
                hph++;
                __syncthreads();
            }
        } else {
            if (tid == 0) mbar_expect(mbb + 16, t > 0 ? 65536u : 32768u);
            __syncthreads();
            if (t == 0) {
                for (int i = tid; i < 8320; i += 256) ((uint32_t*)smA1)[i] = 0u;
            }
            if (tid < 16)
                bulk_g2s(smb + A0_OFF + tid * 2080u,
                         h016 + ((size_t)t * BB + tid) * HID, 2048u, mbb + 16);
            if (t > 0 && tid >= 16 && tid < 32) {
                int b = tid - 16;
                bulk_g2s(smb + A1_OFF + b * 2080u,
                         h116 + ((size_t)b * TT + (t - 1)) * HID, 2048u, mbb + 16);
            }
            mbar_wait(mbb + 16, (unsigned)(hph & 1));
            hph++;
            __syncthreads();
        }

        float hprev = 0.f;
        if (t > 0)
            hprev = (isA ? h0fp : h1fp)[((t + 1) & 1) * 16384 + cta * 256 + tid];

        // ---- K loop over 4 fp16 weight chunks (k=256 each) ----
        wmma::fill_fragment(acc0, 0.f);
        wmma::fill_fragment(acc1, 0.f);
        const __half* Ab = (isA || w < 3) ? smA0 : smA1;

        for (int ch = 0; ch < NCHK; ch++) {
            mbar_wait(mbb + 8 * ws, wpar);
            if (w < ncw) {
                const __half* Ap = Ab + (ch << 8);
                const __half* Bp = ring + ws * chH + w * 16 * WPITCH;
#pragma unroll
                for (int ks = 0; ks < 16; ks++) {
                    wmma::fragment<wmma::matrix_a, 16, 16, 16, __half, wmma::row_major> af;
                    wmma::fragment<wmma::matrix_b, 16, 16, 16, __half, wmma::col_major> bf;
                    wmma::load_matrix_sync(af, Ap + ks * 16, LDHH);
                    wmma::load_matrix_sync(bf, Bp + ks * 16, WPITCH);
                    if (ks & 1) wmma::mma_sync(acc1, af, bf, acc1);
                    else        wmma::mma_sync(acc0, af, bf, acc0);
                }
            }
            __syncthreads();
            if (tid == 0 && gc + 2 < GCMAX) {
                int nch = (int)((gc + 2) & (NCHK - 1));
                mbar_expect(mbb + 8 * ws, chBytes);
                bulk_g2s(smb + RINGB + (uint32_t)ws * chBytes,
                         wbase + (size_t)nch * chH, chBytes, mbb + 8 * ws);
            }
            gc++;
            ws++;
            if (ws == 2) { ws = 0; wpar ^= 1u; }
        }

        // ---- epilogue ----
        if (w < ncw) {
#pragma unroll
            for (int e = 0; e < acc0.num_elements; e++) acc0.x[e] += acc1.x[e];
            wmma::store_matrix_sync(P + w * 256, acc0, 16, wmma::mem_row_major);
        }
        __syncthreads();
        if (isA) mbar_wait(mbb + 24, (unsigned)(t & 1));

        {
            const int o = tid;
            if (isA) {
                const float* gis = GIS + (t & 1) * 768;
                float r = sigmoidf_(gis[o] + P[o] + B0r);
                float u = sigmoidf_(gis[256 + o] + P[256 + o] + B0u);
                float n = tanhf(gis[512 + o] + r * (P[512 + o] + B0n));
                float hnew = (1.f - u) * n + u * hprev;
                h016[((size_t)t * BB + bb) * HID + j] = __float2half_rn(hnew);
                h0fp[(t & 1) * 16384 + cta * 256 + o] = hnew;
            } else {
                float r = sigmoidf_(P[o] + B1ir + P[768 + o] + B1hr);
                float u = sigmoidf_(P[256 + o] + B1iu + P[1024 + o] + B1hu);
                float n = tanhf(P[512 + o] + B1in + r * (P[1280 + o] + B1hn));
                float hnew = (1.f - u) * n + u * hprev;
                h116[((size_t)bb * TT + t) * HID + j] = __float2half_rn(hnew);
                h1fp[(t & 1) * 16384 + cta * 256 + o] = hnew;
            }
        }
        __threadfence();
        __syncthreads();
        if (tid == 0) {
            atomicAdd(&cnt[((isA ? 0 : TT) + t) * CSTRIDE], 1u);
            if (isA && t + 1 < TT) {
                mbar_expect(mbb + 24, 3072u);
                bulk_g2s(smb + GIB + (uint32_t)(((t + 1) & 1) * 3072),
                         gi0 + ((size_t)(t + 1) * 64 + cta) * 3 * 256, 3072u, mbb + 24);
            }
        }
        __syncthreads();
    }
}

extern "C" void kernel_launch(void* const* d_in, const int* in_sizes, int n_in,
                              void* d_out, int out_size)
{
    const int*   seq  = (const int*)d_in[0];
    const float* emb  = (const float*)d_in[1];
    const float* wih0 = (const float*)d_in[2];
    const float* whh0 = (const float*)d_in[3];
    const float* bih0 = (const float*)d_in[4];
    const float* bhh0 = (const float*)d_in[5];
    const float* wih1 = (const float*)d_in[6];
    const float* whh1 = (const float*)d_in[7];
    const float* bih1 = (const float*)d_in[8];
    const float* bhh1 = (const float*)d_in[9];
    const float* wout = (const float*)d_in[10];
    const float* bout = (const float*)d_in[11];
    float* out = (float*)d_out;

    float *gi0, *h0fp, *h1fp; __half *h016, *h116, *wpk0, *wpk1, *emb16, *wih016, *wout16;
    unsigned* cnt;
    cudaGetSymbolAddress((void**)&gi0,    g_gi0);
    cudaGetSymbolAddress((void**)&h016,   g_h016);
    cudaGetSymbolAddress((void**)&h116,   g_h116);
    cudaGetSymbolAddress((void**)&h0fp,   g_h0fp);
    cudaGetSymbolAddress((void**)&h1fp,   g_h1fp);
    cudaGetSymbolAddress((void**)&wpk0,   g_wpk0);
    cudaGetSymbolAddress((void**)&wpk1,   g_wpk1);
    cudaGetSymbolAddress((void**)&emb16,  g_emb16);
    cudaGetSymbolAddress((void**)&wih016, g_wih016);
    cudaGetSymbolAddress((void**)&wout16, g_wout16);
    cudaGetSymbolAddress((void**)&cnt,    g_cnt);

    const int gemm_smem = 73728;
    cudaFuncSetAttribute((const void*)gemm_fp16<1, 1>,
                         cudaFuncAttributeMaxDynamicSharedMemorySize, gemm_smem);
    cudaFuncSetAttribute((const void*)gemm_fp16<0, 0>,
                         cudaFuncAttributeMaxDynamicSharedMemorySize, gemm_smem);
    cudaFuncSetAttribute((const void*)gru_persistent,
                         cudaFuncAttributeMaxDynamicSharedMemorySize, REC_SMEM);

    zero_cnt_k<<<64, 256>>>(cnt);
    f32_to_f16_k<<<4096, 256>>>((const float4*)emb,  (__half2*)emb16,  (long)VOCAB * EMB / 4);
    f32_to_f16_k<<<2048, 256>>>((const float4*)wih0, (__half2*)wih016, (long)H3 * EMB / 4);
    f32_to_f16_k<<<4096, 256>>>((const float4*)wout, (__half2*)wout16, (long)VOCAB * HID / 4);
    repack_k<<<4096, 256>>>(whh0, wih1, whh1, wpk0, wpk1);

    // gi0 packed = gather(emb16) @ wih016^T + b_ih0
    {
        dim3 g(64, H3 / 128);
        gemm_fp16<1, 1><<<g, 256, gemm_smem>>>(emb16, seq, wih016, bih0, gi0,
                                               BB * TT, H3, EMB, EMB);
    }

    gru_persistent<<<128, 256, REC_SMEM>>>(gi0, wpk0, bhh0, wpk1, bih1, bhh1,
                                           h016, h116, h0fp, h1fp, cnt);

    tail_copy_k<<<(BB * HID + 255) / 256, 256>>>(h0fp, h1fp, out);

    // logits = h116 @ wout16^T + b_out
    {
        dim3 g(64, VOCAB / 128);
        gemm_fp16<0, 0><<<g, 256, gemm_smem>>>(h116, nullptr, wout16, bout, out,
                                               BB * TT, VOCAB, HID, HID);
    }
}

// round 17
// speedup vs baseline: 1.2465x; 1.1451x over previous
#include <cuda_runtime.h>
#include <cuda_fp16.h>
#include <mma.h>
#include <math.h>
#include <stdint.h>

using namespace nvcuda;

#define VOCAB 32000
#define EMB   512
#define HID   1024
#define BB    16
#define TT    512
#define H3    3072

// ---- recurrence smem layout (bytes) ----
#define LDHH   1040
#define A0_OFF 0
#define A1_OFF 33280
#define RINGB  66560                    // 2-stage weight ring
#define NCHK   4                        // k-chunks per step (k=256)
#define WPITCH 264
#define CH0H   (48 * WPITCH)
#define CH1H   (96 * WPITCH)
#define PARTB  167936
#define GIB    174080
#define REC_SMEM 180224

#define CSTRIDE 16

// ---- packed projection panels: [tile][kc][128 rows x 72 halves] ----
#define PCH_H   9216                    // halves per chunk block (128*72)
#define PCH_B   18432                   // bytes
#define PROJ_SMEM (2 * 2 * PCH_B)       // 73728: 2 stages x (A + B)

__device__ float  g_gi0[(size_t)TT * BB * H3];      // packed [t][cta][gate][256]
__device__ __half g_h016[(size_t)TT * BB * HID];    // [t][b][H]
__device__ __half g_h116[(size_t)BB * TT * HID];    // [b][t][H] (recurrence staging)
__device__ __half g_h1pk[(size_t)64 * 16 * PCH_H];  // packed proj A
__device__ __half g_wopk[(size_t)250 * 16 * PCH_H]; // packed proj B
__device__ float  g_h0fp[2 * 64 * 256];
__device__ float  g_h1fp[2 * 64 * 256];
__device__ __half g_wpk0[(size_t)64 * NCHK * CH0H];
__device__ __half g_wpk1[(size_t)64 * NCHK * CH1H];
__device__ __half g_emb16[(size_t)VOCAB * EMB];
__device__ __half g_wih016[(size_t)H3 * EMB];
__device__ unsigned g_cnt[2 * TT * CSTRIDE];

__device__ __forceinline__ float sigmoidf_(float x) { return 1.f / (1.f + __expf(-x)); }
__device__ __forceinline__ void mbar_init(uint32_t mbar, unsigned cnt) {
    asm volatile("mbarrier.init.shared.b64 [%0], %1;" :: "r"(mbar), "r"(cnt) : "memory");
}
__device__ __forceinline__ void mbar_expect(uint32_t mbar, unsigned tx) {
    asm volatile("mbarrier.arrive.expect_tx.shared.b64 _, [%0], %1;"
                 :: "r"(mbar), "r"(tx) : "memory");
}
__device__ __forceinline__ void bulk_g2s(uint32_t sdst, const void* gsrc, unsigned bytes,
                                         uint32_t mbar) {
    asm volatile("cp.async.bulk.shared::cta.global.mbarrier::complete_tx::bytes "
                 "[%0], [%1], %2, [%3];"
                 :: "r"(sdst), "l"(gsrc), "r"(bytes), "r"(mbar) : "memory");
}
__device__ __forceinline__ void mbar_wait(uint32_t mbar, unsigned phase) {
    asm volatile(
        "{\n\t"
        ".reg .pred P1;\n\t"
        "LAB_W_%=:\n\t"
        "mbarrier.try_wait.parity.acquire.cta.shared::cta.b64 P1, [%0], %1;\n\t"
        "@P1 bra LAB_D_%=;\n\t"
        "bra LAB_W_%=;\n\t"
        "LAB_D_%=:\n\t"
        "}"
        :: "r"(mbar), "r"(phase) : "memory");
}

__global__ void zero_cnt_k(unsigned* c) {
    int i = blockIdx.x * blockDim.x + threadIdx.x;
    if (i < 2 * TT * CSTRIDE) c[i] = 0u;
}

__global__ void f32_to_f16_k(const float4* __restrict__ src, __half2* __restrict__ dst,
                             long n4) {
    long i = (long)blockIdx.x * blockDim.x + threadIdx.x;
    long stride = (long)gridDim.x * blockDim.x;
    for (; i < n4; i += stride) {
        float4 v = src[i];
        dst[2 * i]     = __floats2half2_rn(v.x, v.y);
        dst[2 * i + 1] = __floats2half2_rn(v.z, v.w);
    }
}

// w_out -> fp16 packed chunk blocks [nt][kc][row][72]
__global__ void pack_wout_k(const float* __restrict__ w, __half* __restrict__ dst) {
    const long total = 250L * 16 * 128 * 8;    // groups of 8 halves
    long i = (long)blockIdx.x * blockDim.x + threadIdx.x;
    const long stride = (long)gridDim.x * blockDim.x;
    for (; i < total; i += stride) {
        int kk = (int)(i & 7) * 8;
        long r = i >> 3;
        int row = (int)(r & 127); r >>= 7;
        int kc = (int)(r & 15); r >>= 4;
        int nt = (int)r;
        const float4* s = (const float4*)(w + ((size_t)nt * 128 + row) * HID + kc * 64 + kk);
        float4 a = s[0], b = s[1];
        __half2 h0 = __floats2half2_rn(a.x, a.y), h1 = __floats2half2_rn(a.z, a.w);
        __half2 h2 = __floats2half2_rn(b.x, b.y), h3 = __floats2half2_rn(b.z, b.w);
        uint4 val;
        val.x = *(uint32_t*)&h0; val.y = *(uint32_t*)&h1;
        val.z = *(uint32_t*)&h2; val.w = *(uint32_t*)&h3;
        *(uint4*)(dst + ((size_t)nt * 16 + kc) * PCH_H + row * 72 + kk) = val;
    }
}

// recurrence weights -> fp16 per-CTA contiguous chunks [cta][ch][row][WPITCH]
__global__ void repack_k(const float* __restrict__ whh0,
                         const float* __restrict__ wih1, const float* __restrict__ whh1,
                         __half* __restrict__ wpk0, __half* __restrict__ wpk1)
{
    const long tot0 = 64L * NCHK * CH0H, tot1 = 64L * NCHK * CH1H;
    long i = (long)blockIdx.x * blockDim.x + threadIdx.x;
    const long stride = (long)gridDim.x * blockDim.x;
    for (; i < tot0 + tot1; i += stride) {
        if (i < tot0) {
            long r = i; int k = (int)(r % WPITCH); r /= WPITCH;
            int row = (int)(r % 48); r /= 48;
            int ch = (int)(r % NCHK); int cta = (int)(r / NCHK);
            __half v = __float2half(0.f);
            if (k < 256)
                v = __float2half_rn(
                    whh0[((size_t)((row >> 4) * HID + cta * 16 + (row & 15))) * HID
                         + ch * 256 + k]);
            wpk0[i] = v;
        } else {
            long r = i - tot0; int k = (int)(r % WPITCH); r /= WPITCH;
            int row = (int)(r % 96); r /= 96;
            int ch = (int)(r % NCHK); int cta = (int)(r / NCHK);
            __half v = __float2half(0.f);
            if (k < 256) {
                const float* W = (row < 48) ? wih1 : whh1;
                int rr = (row < 48) ? row : row - 48;
                v = __float2half_rn(
                    W[((size_t)((rr >> 4) * HID + cta * 16 + (rr & 15))) * HID
                      + ch * 256 + k]);
            }
            wpk1[i - tot0] = v;
        }
    }
}

__global__ void tail_copy_k(const float* __restrict__ h0fp,
                            const float* __restrict__ h1fp,
                            float* __restrict__ out) {
    int i = blockIdx.x * blockDim.x + threadIdx.x;
    if (i < BB * HID) {
        int b = i >> 10, j = i & 1023;
        int cta = j >> 4, o = b * 16 + (j & 15);
        out[(size_t)BB * TT * VOCAB + i]            = h0fp[16384 + cta * 256 + o];
        out[(size_t)BB * TT * VOCAB + BB * HID + i] = h1fp[16384 + cta * 256 + o];
    }
}

// ---------------------------------------------------------------------------
// gi0 GEMM (gather), unchanged proven path.
// ---------------------------------------------------------------------------
template <int GATHER, int STORE_GI>
__global__ void __launch_bounds__(256, 2)
gemm_fp16(const __half* __restrict__ A, const int* __restrict__ seq,
          const __half* __restrict__ Bm, const float* __restrict__ bias,
          float* __restrict__ C, int M, int N, int K, int lda)
{
    extern __shared__ __half hsm[];
    __shared__ float biasS[16][136];
    __shared__ int tokS[128];
    __shared__ __align__(8) unsigned long long mb_[2];

    const int tid = threadIdx.x;
    const int m0 = blockIdx.x * 128;
    const int n0 = blockIdx.y * 128;

    if (GATHER && tid < 128) {
        int m = m0 + tid;
        tokS[tid] = seq[(m & 15) * TT + (m >> 4)];
    }
    for (int i = tid; i < 2048; i += 256)
        biasS[i >> 7][i & 127] = bias[n0 + (i & 127)];

    const uint32_t sb = (uint32_t)__cvta_generic_to_shared(hsm);
    const uint32_t mbb = (uint32_t)__cvta_generic_to_shared(mb_);
    const int KC = K >> 6;

    if (tid == 0) {
        mbar_init(mbb, 1); mbar_init(mbb + 8, 1);
        mbar_expect(mbb, 32768u); mbar_expect(mbb + 8, 32768u);
    }
    __syncthreads();

    auto issue = [&](int kc, int st) {
        const int k0 = kc << 6;
        const int row = tid & 127;
        const uint32_t stb = sb + (uint32_t)st * 36864u;
        if (tid < 128) {
            const __half* src = GATHER ? (A + (size_t)tokS[row] * lda + k0)
                                       : (A + (size_t)(m0 + row) * lda + k0);
            bulk_g2s(stb + row * 144u, src, 128u, mbb + 8u * st);
        } else {
            bulk_g2s(stb + 18432u + row * 144u,
                     Bm + (size_t)(n0 + row) * K + k0, 128u, mbb + 8u * st);
        }
    };
    issue(0, 0);
    issue(1, 1);

    const int warpId = tid >> 5;
    const int wm = warpId >> 1;
    const int wn = warpId & 1;

    wmma::fragment<wmma::accumulator, 16, 16, 16, float> acc[2][4];
#pragma unroll
    for (int mi = 0; mi < 2; mi++)
#pragma unroll
        for (int ni = 0; ni < 4; ni++)
            wmma::load_matrix_sync(acc[mi][ni], &biasS[0][wn * 64 + ni * 16], 136,
                                   wmma::mem_row_major);

    for (int kc = 0; kc < KC; kc++) {
        const int st = kc & 1;
        mbar_wait(mbb + 8u * st, (unsigned)((kc >> 1) & 1));
        const __half* As = hsm + st * 18432;
        const __half* Bs = As + 9216;
#pragma unroll
        for (int ks = 0; ks < 4; ks++) {
            wmma::fragment<wmma::matrix_a, 16, 16, 16, __half, wmma::row_major> a[2];
            wmma::fragment<wmma::matrix_b, 16, 16, 16, __half, wmma::col_major> b[4];
#pragma unroll
            for (int mi = 0; mi < 2; mi++)
                wmma::load_matrix_sync(a[mi], As + (wm * 32 + mi * 16) * 72 + ks * 16, 72);
#pragma unroll
            for (int ni = 0; ni < 4; ni++)
                wmma::load_matrix_sync(b[ni], Bs + (wn * 64 + ni * 16) * 72 + ks * 16, 72);
#pragma unroll
            for (int mi = 0; mi < 2; mi++)
#pragma unroll
                for (int ni = 0; ni < 4; ni++)
                    wmma::mma_sync(acc[mi][ni], a[mi], b[ni], acc[mi][ni]);
        }
        __syncthreads();
        if (kc + 2 < KC) {
            if (tid == 0) mbar_expect(mbb + 8u * st, 32768u);
            __syncthreads();
            issue(kc + 2, st);
        }
    }

#pragma unroll
    for (int mi = 0; mi < 2; mi++)
#pragma unroll
        for (int ni = 0; ni < 4; ni++) {
            int mrow = m0 + wm * 32 + mi * 16;
            int ncol = n0 + wn * 64 + ni * 16;
            if (STORE_GI) {
                int t = mrow >> 4;
                int gate = ncol >> 10;
                int colblk = (ncol & 1023) >> 4;
                wmma::store_matrix_sync(
                    C + (((size_t)t * 64 + colblk) * 3 + gate) * 256,
                    acc[mi][ni], 16, wmma::mem_row_major);
            } else {
                wmma::store_matrix_sync(C + (size_t)mrow * N + ncol,
                                        acc[mi][ni], N, wmma::mem_row_major);
            }
        }
}

// ---------------------------------------------------------------------------
// Projection GEMM on packed panels: one bulk per operand per chunk (tid 0),
// one syncthreads per chunk. 2-stage ring, 2 CTAs/SM.
// ---------------------------------------------------------------------------
__global__ void __launch_bounds__(256, 2)
proj_gemm(const __half* __restrict__ Apk, const __half* __restrict__ Bpk,
          const float* __restrict__ bias, float* __restrict__ C)
{
    extern __shared__ __half hsm[];   // 2 stages x (A 9216 | B 9216) halves
    __shared__ float biasS[16][136];
    __shared__ __align__(8) unsigned long long mb_[2];

    const int tid = threadIdx.x;
    const int mt = blockIdx.x;    // 0..63  (fastest -> A panel L2-resident)
    const int nt = blockIdx.y;    // 0..249

    for (int i = tid; i < 2048; i += 256)
        biasS[i >> 7][i & 127] = bias[nt * 128 + (i & 127)];

    const uint32_t sb = (uint32_t)__cvta_generic_to_shared(hsm);
    const uint32_t mbb = (uint32_t)__cvta_generic_to_shared(mb_);
    const __half* Abase = Apk + (size_t)mt * 16 * PCH_H;
    const __half* Bbase = Bpk + (size_t)nt * 16 * PCH_H;

    if (tid == 0) {
        mbar_init(mbb, 1); mbar_init(mbb + 8, 1);
#pragma unroll
        for (int s = 0; s < 2; s++) {
            mbar_expect(mbb + 8u * s, 2u * PCH_B);
            bulk_g2s(sb + s * 2 * PCH_B,         Abase + (size_t)s * PCH_H, PCH_B, mbb + 8u * s);
            bulk_g2s(sb + s * 2 * PCH_B + PCH_B, Bbase + (size_t)s * PCH_H, PCH_B, mbb + 8u * s);
        }
    }
    __syncthreads();

    const int warpId = tid >> 5;
    const int wm = warpId >> 1;
    const int wn = warpId & 1;

    wmma::fragment<wmma::accumulator, 16, 16, 16, float> acc[2][4];
#pragma unroll
    for (int mi = 0; mi < 2; mi++)
#pragma unroll
        for (int ni = 0; ni < 4; ni++)
            wmma::load_matrix_sync(acc[mi][ni], &biasS[0][wn * 64 + ni * 16], 136,
                                   wmma::mem_row_major);

    for (int kc = 0; kc < 16; kc++) {
        const int st = kc & 1;
        mbar_wait(mbb + 8u * st, (unsigned)((kc >> 1) & 1));
        const __half* As = hsm + st * 2 * PCH_H;
        const __half* Bs = As + PCH_H;
#pragma unroll
        for (int ks = 0; ks < 4; ks++) {
            wmma::fragment<wmma::matrix_a, 16, 16, 16, __half, wmma::row_major> a[2];
            wmma::fragment<wmma::matrix_b, 16, 16, 16, __half, wmma::col_major> b[4];
#pragma unroll
            for (int mi = 0; mi < 2; mi++)
                wmma::load_matrix_sync(a[mi], As + (wm * 32 + mi * 16) * 72 + ks * 16, 72);
#pragma unroll
            for (int ni = 0; ni < 4; ni++)
                wmma::load_matrix_sync(b[ni], Bs + (wn * 64 + ni * 16) * 72 + ks * 16, 72);
#pragma unroll
            for (int mi = 0; mi < 2; mi++)
#pragma unroll
                for (int ni = 0; ni < 4; ni++)
                    wmma::mma_sync(acc[mi][ni], a[mi], b[ni], acc[mi][ni]);
        }
        __syncthreads();   // stage consumed by all warps
        if (tid == 0 && kc + 2 < 16) {
            const int nc = kc + 2;
            mbar_expect(mbb + 8u * st, 2u * PCH_B);
            bulk_g2s(sb + st * 2 * PCH_B,         Abase + (size_t)nc * PCH_H, PCH_B, mbb + 8u * st);
            bulk_g2s(sb + st * 2 * PCH_B + PCH_B, Bbase + (size_t)nc * PCH_H, PCH_B, mbb + 8u * st);
        }
    }

#pragma unroll
    for (int mi = 0; mi < 2; mi++)
#pragma unroll
        for (int ni = 0; ni < 4; ni++)
            wmma::store_matrix_sync(
                C + ((size_t)mt * 128 + wm * 32 + mi * 16) * VOCAB
                  + nt * 128 + wn * 64 + ni * 16,
                acc[mi][ni], VOCAB, wmma::mem_row_major);
}

// ---------------------------------------------------------------------------
// Persistent fp16 GRU: 128 CTAs x 256 thr, 1 CTA/SM, k-chunk 256 (4/step).
// ---------------------------------------------------------------------------
__global__ void __launch_bounds__(256, 1)
gru_persistent(const float* __restrict__ gi0,
               const __half* __restrict__ wpk0, const float* __restrict__ bhh0,
               const __half* __restrict__ wpk1, const float* __restrict__ bih1,
               const float* __restrict__ bhh1,
               __half* __restrict__ h016, __half* __restrict__ h116,
               __half* __restrict__ h1pk,
               float* __restrict__ h0fp, float* __restrict__ h1fp,
               unsigned* __restrict__ cnt)
{
    extern __shared__ char smraw[];
    __half* smA0 = (__half*)smraw;
    __half* smA1 = (__half*)(smraw + A1_OFF);
    __half* ring = (__half*)(smraw + RINGB);
    float*  P    = (float*)(smraw + PARTB);
    float*  GIS  = (float*)(smraw + GIB);
    __shared__ __align__(8) unsigned long long mbars[4];

    const int tid = threadIdx.x;
    const int w = tid >> 5;
    const bool isA = blockIdx.x < 64;
    const int cta = isA ? blockIdx.x : (blockIdx.x - 64);
    const int c0 = cta * 16;
    const int ncw = isA ? 3 : 6;
    const int bb = tid >> 4, jl = tid & 15;
    const int j = c0 + jl;
    volatile unsigned* vc = cnt;

    const __half* wbase = isA ? (wpk0 + (size_t)cta * NCHK * CH0H)
                              : (wpk1 + (size_t)cta * NCHK * CH1H);
    const int chH = isA ? CH0H : CH1H;
    const unsigned chBytes = (unsigned)(chH * 2);

    const uint32_t smb = (uint32_t)__cvta_generic_to_shared(smraw);
    const uint32_t mbb = (uint32_t)__cvta_generic_to_shared(mbars);

    float B0r = 0.f, B0u = 0.f, B0n = 0.f;
    float B1ir = 0.f, B1iu = 0.f, B1in = 0.f, B1hr = 0.f, B1hu = 0.f, B1hn = 0.f;
    if (isA) {
        B0r = bhh0[j]; B0u = bhh0[HID + j]; B0n = bhh0[2 * HID + j];
    } else {
        B1ir = bih1[j]; B1iu = bih1[HID + j]; B1in = bih1[2 * HID + j];
        B1hr = bhh1[j]; B1hu = bhh1[HID + j]; B1hn = bhh1[2 * HID + j];
    }

    if (tid == 0) {
        for (int s = 0; s < 4; s++) mbar_init(mbb + 8 * s, 1);
#pragma unroll
        for (int s = 0; s < 2; s++) {
            mbar_expect(mbb + 8 * s, chBytes);
            bulk_g2s(smb + RINGB + (uint32_t)s * chBytes, wbase + (size_t)s * chH,
                     chBytes, mbb + 8 * s);
        }
        if (isA) {
            mbar_expect(mbb + 24, 3072u);
            bulk_g2s(smb + GIB, gi0 + (size_t)cta * 3 * 256, 3072u, mbb + 24);
        }
    }
    __syncthreads();

    int ws = 0;
    unsigned wpar = 0;
    long gc = 0;
    const long GCMAX = (long)TT * NCHK;
    int hph = 0;

    wmma::fragment<wmma::accumulator, 16, 16, 16, float> acc0, acc1;

    for (int t = 0; t < TT; t++) {
        if (tid == 0) {
            unsigned sp;
            if (isA) {
                if (t) { sp = 0; while (vc[(t - 1) * CSTRIDE] < 64u) { if (++sp > 16) __nanosleep(32); } }
            } else {
                sp = 0; while (vc[t * CSTRIDE] < 64u) { if (++sp > 16) __nanosleep(32); }
                if (t) { sp = 0; while (vc[(TT + t - 1) * CSTRIDE] < 64u) { if (++sp > 16) __nanosleep(32); } }
            }
        }
        __syncthreads();
        __threadfence();

        if (isA) {
            if (t == 0) {
                for (int i = tid; i < 8320; i += 256) ((uint32_t*)smA0)[i] = 0u;
                __syncthreads();
            } else {
                if (tid == 0) mbar_expect(mbb + 16, 32768u);
                __syncthreads();
                if (tid < 16)
                    bulk_g2s(smb + A0_OFF + tid * 2080u,
                             h016 + ((size_t)(t - 1) * BB + tid) * HID, 2048u, mbb + 16);
                mbar_wait(mbb + 16, (unsigned)(hph & 1));
                hph++;
            }
        } else {
            if (tid == 0) mbar_expect(mbb + 16, t > 0 ? 65536u : 32768u);
            __syncthreads();
            if (t == 0) {
                for (int i = tid; i < 8320; i += 256) ((uint32_t*)smA1)[i] = 0u;
            }
            if (tid < 16)
                bulk_g2s(smb + A0_OFF + tid * 2080u,
                         h016 + ((size_t)t * BB + tid) * HID, 2048u, mbb + 16);
            if (t > 0 && tid >= 16 && tid < 32) {
                int b = tid - 16;
                bulk_g2s(smb + A1_OFF + b * 2080u,
                         h116 + ((size_t)b * TT + (t - 1)) * HID, 2048u, mbb + 16);
            }
            mbar_wait(mbb + 16, (unsigned)(hph & 1));
            hph++;
            if (t == 0) __syncthreads();   // protect zero-fill of smA1
        }

        float hprev = 0.f;
        if (t > 0)
            hprev = (isA ? h0fp : h1fp)[((t + 1) & 1) * 16384 + cta * 256 + tid];

        wmma::fill_fragment(acc0, 0.f);
        wmma::fill_fragment(acc1, 0.f);
        const __half* Ab = (isA || w < 3) ? smA0 : smA1;

        for (int ch = 0; ch < NCHK; ch++) {
            mbar_wait(mbb + 8 * ws, wpar);
            if (w < ncw) {
                const __half* Ap = Ab + (ch << 8);
                const __half* Bp = ring + ws * chH + w * 16 * WPITCH;
#pragma unroll
                for (int ks = 0; ks < 16; ks++) {
                    wmma::fragment<wmma::matrix_a, 16, 16, 16, __half, wmma::row_major> af;
                    wmma::fragment<wmma::matrix_b, 16, 16, 16, __half, wmma::col_major> bf;
                    wmma::load_matrix_sync(af, Ap + ks * 16, LDHH);
                    wmma::load_matrix_sync(bf, Bp + ks * 16, WPITCH);
                    if (ks & 1) wmma::mma_sync(acc1, af, bf, acc1);
                    else        wmma::mma_sync(acc0, af, bf, acc0);
                }
            }
            __syncthreads();
            if (tid == 0 && gc + 2 < GCMAX) {
                int nch = (int)((gc + 2) & (NCHK - 1));
                mbar_expect(mbb + 8 * ws, chBytes);
                bulk_g2s(smb + RINGB + (uint32_t)ws * chBytes,
                         wbase + (size_t)nch * chH, chBytes, mbb + 8 * ws);
            }
            gc++;
            ws++;
            if (ws == 2) { ws = 0; wpar ^= 1u; }
        }

        if (w < ncw) {
#pragma unroll
            for (int e = 0; e < acc0.num_elements; e++) acc0.x[e] += acc1.x[e];
            wmma::store_matrix_sync(P + w * 256, acc0, 16, wmma::mem_row_major);
        }
        __syncthreads();
        if (isA) mbar_wait(mbb + 24, (unsigned)(t & 1));

        {
            const int o = tid;
            if (isA) {
                const float* gis = GIS + (t & 1) * 768;
                float r = sigmoidf_(gis[o] + P[o] + B0r);
                float u = sigmoidf_(gis[256 + o] + P[256 + o] + B0u);
                float n = tanhf(gis[512 + o] + r * (P[512 + o] + B0n));
                float hnew = (1.f - u) * n + u * hprev;
                h016[((size_t)t * BB + bb) * HID + j] = __float2half_rn(hnew);
                h0fp[(t & 1) * 16384 + cta * 256 + o] = hnew;
            } else {
                float r = sigmoidf_(P[o] + B1ir + P[768 + o] + B1hr);
                float u = sigmoidf_(P[256 + o] + B1iu + P[1024 + o] + B1hu);
                float n = tanhf(P[512 + o] + B1in + r * (P[1280 + o] + B1hn));
                float hnew = (1.f - u) * n + u * hprev;
                __half hv = __float2half_rn(hnew);
                h116[((size_t)bb * TT + t) * HID + j] = hv;
                h1fp[(t & 1) * 16384 + cta * 256 + o] = hnew;
                // packed proj-A copy: m = bb*TT+t
                int m = bb * TT + t;
                int mt = m >> 7, rw = m & 127;
                int kc = j >> 6, kk = j & 63;
                h1pk[((size_t)mt * 16 + kc) * PCH_H + rw * 72 + kk] = hv;
            }
        }
        __threadfence();
        __syncthreads();
        if (tid == 0) {
            atomicAdd(&cnt[((isA ? 0 : TT) + t) * CSTRIDE], 1u);
            if (isA && t + 1 < TT) {
                mbar_expect(mbb + 24, 3072u);
                bulk_g2s(smb + GIB + (uint32_t)(((t + 1) & 1) * 3072),
                         gi0 + ((size_t)(t + 1) * 64 + cta) * 3 * 256, 3072u, mbb + 24);
            }
        }
        __syncthreads();
    }
}

extern "C" void kernel_launch(void* const* d_in, const int* in_sizes, int n_in,
                              void* d_out, int out_size)
{
    const int*   seq  = (const int*)d_in[0];
    const float* emb  = (const float*)d_in[1];
    const float* wih0 = (const float*)d_in[2];
    const float* whh0 = (const float*)d_in[3];
    const float* bih0 = (const float*)d_in[4];
    const float* bhh0 = (const float*)d_in[5];
    const float* wih1 = (const float*)d_in[6];
    const float* whh1 = (const float*)d_in[7];
    const float* bih1 = (const float*)d_in[8];
    const float* bhh1 = (const float*)d_in[9];
    const float* wout = (const float*)d_in[10];
    const float* bout = (const float*)d_in[11];
    float* out = (float*)d_out;

    float *gi0, *h0fp, *h1fp;
    __half *h016, *h116, *h1pk, *wopk, *wpk0, *wpk1, *emb16, *wih016;
    unsigned* cnt;
    cudaGetSymbolAddress((void**)&gi0,    g_gi0);
    cudaGetSymbolAddress((void**)&h016,   g_h016);
    cudaGetSymbolAddress((void**)&h116,   g_h116);
    cudaGetSymbolAddress((void**)&h1pk,   g_h1pk);
    cudaGetSymbolAddress((void**)&wopk,   g_wopk);
    cudaGetSymbolAddress((void**)&h0fp,   g_h0fp);
    cudaGetSymbolAddress((void**)&h1fp,   g_h1fp);
    cudaGetSymbolAddress((void**)&wpk0,   g_wpk0);
    cudaGetSymbolAddress((void**)&wpk1,   g_wpk1);
    cudaGetSymbolAddress((void**)&emb16,  g_emb16);
    cudaGetSymbolAddress((void**)&wih016, g_wih016);
    cudaGetSymbolAddress((void**)&cnt,    g_cnt);

    const int gemm_smem = 73728;
    cudaFuncSetAttribute((const void*)gemm_fp16<1, 1>,
                         cudaFuncAttributeMaxDynamicSharedMemorySize, gemm_smem);
    cudaFuncSetAttribute((const void*)proj_gemm,
                         cudaFuncAttributeMaxDynamicSharedMemorySize, PROJ_SMEM);
    cudaFuncSetAttribute((const void*)gru_persistent,
                         cudaFuncAttributeMaxDynamicSharedMemorySize, REC_SMEM);

    zero_cnt_k<<<64, 256>>>(cnt);
    f32_to_f16_k<<<4096, 256>>>((const float4*)emb,  (__half2*)emb16,  (long)VOCAB * EMB / 4);
    f32_to_f16_k<<<2048, 256>>>((const float4*)wih0, (__half2*)wih016, (long)H3 * EMB / 4);
    pack_wout_k<<<8192, 256>>>(wout, wopk);
    repack_k<<<4096, 256>>>(whh0, wih1, whh1, wpk0, wpk1);

    // gi0 packed = gather(emb16) @ wih016^T + b_ih0
    {
        dim3 g(64, H3 / 128);
        gemm_fp16<1, 1><<<g, 256, gemm_smem>>>(emb16, seq, wih016, bih0, gi0,
                                               BB * TT, H3, EMB, EMB);
    }

    gru_persistent<<<128, 256, REC_SMEM>>>(gi0, wpk0, bhh0, wpk1, bih1, bhh1,
                                           h016, h116, h1pk, h0fp, h1fp, cnt);

    tail_copy_k<<<(BB * HID + 255) / 256, 256>>>(h0fp, h1fp, out);

    // logits = h1pk @ wopk^T + b_out (packed panels)
    {
        dim3 g(64, 250);
        proj_gemm<<<g, 256, PROJ_SMEM>>>(h1pk, wopk, bout, out);
    }
}